// round 1
// baseline (speedup 1.0000x reference)
#include <cuda_runtime.h>
#include <cstdint>

// ---------------------------------------------------------------------------
// MGDCF diffusion: h_{t+1} = BETA * A_norm h_t + ALPHA * h0, K=4 steps.
// A_norm = D^-1/2 (A_bidirected + I) D^-1/2 over N = 300000 homo nodes.
// Strategy: build dst-ordered CSR once per launch (no global sort; warp-
// aggregated segment allocation), then 4 gather-only SpMM passes, warp/row.
// ---------------------------------------------------------------------------

#define NUSERS 200000
#define NITEMS 100000
#define NN     300000              // total nodes
#define NE     1000000             // user-item pairs
#define DD     64                  // feature dim

static constexpr float ALPHA_C = 0.1f;
static constexpr float BETA_C  = 0.9f;
// GAMMA = BETA^4 + ALPHA*(1+.9+.81+.729) = 0.6561 + 0.3439 = 1.0 (exact-ish)
static constexpr double GAMMA_D =
    (0.9 * 0.9 * 0.9 * 0.9) + 0.1 * (1.0 + 0.9 + 0.81 + 0.729);
static constexpr float INV_GAMMA = (float)(1.0 / GAMMA_D);

// ------------------------- device scratch (static) -------------------------
__device__ float g_h[2][(size_t)NN * DD];   // ping-pong feature buffers (153.6 MB)
__device__ int   g_cnt[NN];                 // degree incl. self loop
__device__ float g_norm[NN];                // deg^-1/2
__device__ int   g_rowstart[NN];            // CSR segment start (unordered alloc)
__device__ int   g_cursor[NN];              // fill cursors
__device__ uint2 g_edge[2 * NE];            // (src, norm[src] as bits), 16 MB
__device__ int   g_alloc;                   // global segment allocator

// ------------------------------ build kernels ------------------------------

__global__ void init_kernel() {
    int v = blockIdx.x * blockDim.x + threadIdx.x;
    if (v < NN) g_cnt[v] = 1;               // self loop
    if (v == 0) g_alloc = 0;
}

__global__ void count_kernel(const int* __restrict__ uidx,
                             const int* __restrict__ iidx) {
    int e = blockIdx.x * blockDim.x + threadIdx.x;
    if (e >= NE) return;
    int u  = uidx[e];
    int it = iidx[e] + NUSERS;
    atomicAdd(&g_cnt[u], 1);
    atomicAdd(&g_cnt[it], 1);
}

// Per-node: norm = rsqrt(deg); allocate a contiguous CSR segment of length
// (deg-1) via warp-aggregated atomicAdd on the global allocator.
__global__ void alloc_kernel() {
    int v    = blockIdx.x * blockDim.x + threadIdx.x;
    int lane = threadIdx.x & 31;
    int c = 0;
    if (v < NN) {
        int d = g_cnt[v];
        c = d - 1;                           // real in-edges (excl. self loop)
        g_norm[v] = rsqrtf((float)d);
    }
    // inclusive warp scan of c
    int inc = c;
    #pragma unroll
    for (int o = 1; o < 32; o <<= 1) {
        int t = __shfl_up_sync(0xFFFFFFFFu, inc, o);
        if (lane >= o) inc += t;
    }
    int total = __shfl_sync(0xFFFFFFFFu, inc, 31);
    int base = 0;
    if (lane == 31) base = atomicAdd(&g_alloc, total);
    base = __shfl_sync(0xFFFFFFFFu, base, 31);
    if (v < NN) {
        int st = base + inc - c;
        g_rowstart[v] = st;
        g_cursor[v]   = st;
    }
}

__global__ void fill_kernel(const int* __restrict__ uidx,
                            const int* __restrict__ iidx) {
    int e = blockIdx.x * blockDim.x + threadIdx.x;
    if (e >= NE) return;
    int u  = uidx[e];
    int it = iidx[e] + NUSERS;
    float nu = g_norm[u];
    float ni = g_norm[it];
    // edge u -> it  (dst = it), payload excludes norm[dst]
    int p0 = atomicAdd(&g_cursor[it], 1);
    g_edge[p0] = make_uint2((unsigned)u, __float_as_uint(nu));
    // edge it -> u  (dst = u)
    int p1 = atomicAdd(&g_cursor[u], 1);
    g_edge[p1] = make_uint2((unsigned)it, __float_as_uint(ni));
}

// ------------------------------- SpMM kernel -------------------------------
// One warp per destination row; each lane owns a float2 (2 columns).
// h_dst[v] = fs * ( BETA*norm[v]*sum_j norm[src_j]*h_src[src_j]
//                 + BETA*norm[v]^2*h_src[v] + ALPHA*x[v] )
__global__ void __launch_bounds__(256)
spmm_kernel(int src_sel, int dst_sel,
            const float* __restrict__ x, float* __restrict__ dout, float fs) {
    int warp = blockIdx.x * (blockDim.x >> 5) + (threadIdx.x >> 5);
    int lane = threadIdx.x & 31;
    if (warp >= NN) return;
    const int row = warp;

    const float* __restrict__ hsrc = (src_sel < 0) ? x    : &g_h[src_sel][0];
    float*       __restrict__ hdst = (dst_sel < 0) ? dout : &g_h[dst_sel][0];

    const int   st  = g_rowstart[row];
    const int   len = g_cnt[row] - 1;
    const float nv  = g_norm[row];

    float ax = 0.f, ay = 0.f;
    int j = 0;
    // 2-way unroll for memory-level parallelism within the warp
    for (; j + 2 <= len; j += 2) {
        uint2 e0 = g_edge[st + j];
        uint2 e1 = g_edge[st + j + 1];
        float2 v0 = ((const float2*)(hsrc + (size_t)e0.x * DD))[lane];
        float2 v1 = ((const float2*)(hsrc + (size_t)e1.x * DD))[lane];
        float w0 = __uint_as_float(e0.y);
        float w1 = __uint_as_float(e1.y);
        ax = fmaf(w0, v0.x, ax);  ay = fmaf(w0, v0.y, ay);
        ax = fmaf(w1, v1.x, ax);  ay = fmaf(w1, v1.y, ay);
    }
    if (j < len) {
        uint2 e0 = g_edge[st + j];
        float2 v0 = ((const float2*)(hsrc + (size_t)e0.x * DD))[lane];
        float w0 = __uint_as_float(e0.y);
        ax = fmaf(w0, v0.x, ax);  ay = fmaf(w0, v0.y, ay);
    }

    float2 sh = ((const float2*)(hsrc + (size_t)row * DD))[lane];  // self loop
    float2 x0 = ((const float2*)(x    + (size_t)row * DD))[lane];  // h0 term

    const float cn = BETA_C * nv;          // neighbor-sum coefficient
    const float cs = BETA_C * nv * nv;     // self-loop coefficient (= BETA/deg)

    float rx = (fmaf(cn, ax, fmaf(cs, sh.x, ALPHA_C * x0.x))) * fs;
    float ry = (fmaf(cn, ay, fmaf(cs, sh.y, ALPHA_C * x0.y))) * fs;

    ((float2*)(hdst + (size_t)row * DD))[lane] = make_float2(rx, ry);
}

// --------------------------------- launch ----------------------------------
extern "C" void kernel_launch(void* const* d_in, const int* in_sizes, int n_in,
                              void* d_out, int out_size) {
    const float* x    = (const float*)d_in[0];
    const int*   uidx = (const int*)  d_in[1];
    const int*   iidx = (const int*)  d_in[2];
    float*       out  = (float*)d_out;

    const int T = 256;
    // ---- CSR build (per launch; amortized over 4 SpMM steps) ----
    init_kernel <<<(NN + T - 1) / T, T>>>();
    count_kernel<<<(NE + T - 1) / T, T>>>(uidx, iidx);
    alloc_kernel<<<(NN + T - 1) / T, T>>>();
    fill_kernel <<<(NE + T - 1) / T, T>>>(uidx, iidx);

    // ---- K = 4 diffusion steps (ping-pong; last writes d_out) ----
    const int warps_per_blk = T / 32;                 // 8 rows / block
    const int spmm_blocks   = (NN + warps_per_blk - 1) / warps_per_blk;
    spmm_kernel<<<spmm_blocks, T>>>(-1, 0, x, out, 1.0f);        // x    -> h[0]
    spmm_kernel<<<spmm_blocks, T>>>( 0, 1, x, out, 1.0f);        // h[0] -> h[1]
    spmm_kernel<<<spmm_blocks, T>>>( 1, 0, x, out, 1.0f);        // h[1] -> h[0]
    spmm_kernel<<<spmm_blocks, T>>>( 0, -1, x, out, INV_GAMMA);  // h[0] -> out
}

// round 2
// speedup vs baseline: 1.3320x; 1.3320x over previous
#include <cuda_runtime.h>
#include <cstdint>

// ---------------------------------------------------------------------------
// MGDCF diffusion: h_{t+1} = BETA * A_norm h_t + ALPHA * h0, K=4 steps.
// Round 2: SpMM restructured — 16 lanes/row (float4 / LDG.128), batched edge
// fetch with shuffle broadcast, predicated unrolled gathers for deep MLP.
// ---------------------------------------------------------------------------

#define NUSERS 200000
#define NITEMS 100000
#define NN     300000              // total nodes (even -> exact warp tiling)
#define NE     1000000             // user-item pairs
#define DD     64                  // feature dim

static constexpr float ALPHA_C = 0.1f;
static constexpr float BETA_C  = 0.9f;
static constexpr double GAMMA_D =
    (0.9 * 0.9 * 0.9 * 0.9) + 0.1 * (1.0 + 0.9 + 0.81 + 0.729);   // = 1.0
static constexpr float INV_GAMMA = (float)(1.0 / GAMMA_D);

// ------------------------- device scratch (static) -------------------------
__device__ float g_h[2][(size_t)NN * DD];   // ping-pong feature buffers
__device__ int   g_cnt[NN];                 // degree incl. self loop
__device__ float g_norm[NN];                // deg^-1/2
__device__ int2  g_rowinfo[NN];             // (segment start, real in-degree)
__device__ int   g_cursor[NN];              // fill cursors
__device__ uint2 g_edge[2 * NE];            // (src, norm[src] bits), 16 MB
__device__ int   g_alloc;                   // global segment allocator

// ------------------------------ build kernels ------------------------------

__global__ void init_kernel() {
    int v = blockIdx.x * blockDim.x + threadIdx.x;
    if (v < NN) g_cnt[v] = 1;               // self loop
    if (v == 0) g_alloc = 0;
}

__global__ void count_kernel(const int* __restrict__ uidx,
                             const int* __restrict__ iidx) {
    int e = blockIdx.x * blockDim.x + threadIdx.x;
    if (e >= NE) return;
    int u  = uidx[e];
    int it = iidx[e] + NUSERS;
    atomicAdd(&g_cnt[u], 1);
    atomicAdd(&g_cnt[it], 1);
}

// Per-node: norm = rsqrt(deg); allocate contiguous CSR segment of length
// (deg-1) via warp-scanned atomicAdd on the global allocator.
__global__ void alloc_kernel() {
    int v    = blockIdx.x * blockDim.x + threadIdx.x;
    int lane = threadIdx.x & 31;
    int c = 0;
    if (v < NN) {
        int d = g_cnt[v];
        c = d - 1;
        g_norm[v] = rsqrtf((float)d);
    }
    int inc = c;
    #pragma unroll
    for (int o = 1; o < 32; o <<= 1) {
        int t = __shfl_up_sync(0xFFFFFFFFu, inc, o);
        if (lane >= o) inc += t;
    }
    int total = __shfl_sync(0xFFFFFFFFu, inc, 31);
    int base = 0;
    if (lane == 31) base = atomicAdd(&g_alloc, total);
    base = __shfl_sync(0xFFFFFFFFu, base, 31);
    if (v < NN) {
        int st = base + inc - c;
        g_rowinfo[v] = make_int2(st, c);
        g_cursor[v]  = st;
    }
}

__global__ void fill_kernel(const int* __restrict__ uidx,
                            const int* __restrict__ iidx) {
    int e = blockIdx.x * blockDim.x + threadIdx.x;
    if (e >= NE) return;
    int u  = uidx[e];
    int it = iidx[e] + NUSERS;
    float nu = g_norm[u];
    float ni = g_norm[it];
    int p0 = atomicAdd(&g_cursor[it], 1);
    g_edge[p0] = make_uint2((unsigned)u, __float_as_uint(nu));
    int p1 = atomicAdd(&g_cursor[u], 1);
    g_edge[p1] = make_uint2((unsigned)it, __float_as_uint(ni));
}

// ------------------------------- SpMM kernel -------------------------------
// Two rows per warp: 16 lanes per destination row, each lane owns a float4
// (4 consecutive columns). Edge batch is fetched coalesced (one uint2 per
// lane) and broadcast via width-16 shuffles; gathers are predicated and
// fully unrolled for deep memory-level parallelism.
__global__ void __launch_bounds__(256)
spmm_kernel(int src_sel, int dst_sel,
            const float* __restrict__ x, float* __restrict__ dout, float fs) {
    const int lane = threadIdx.x & 31;
    const int sub  = lane & 15;             // lane within the 16-lane row team
    const int half = lane >> 4;             // which row of this warp
    const int warp = blockIdx.x * (blockDim.x >> 5) + (threadIdx.x >> 5);
    const int row  = warp * 2 + half;
    if (row >= NN) return;                  // never taken (exact tiling)

    const float* __restrict__ hsrc = (src_sel < 0) ? x    : &g_h[src_sel][0];
    float*       __restrict__ hdst = (dst_sel < 0) ? dout : &g_h[dst_sel][0];

    const int2  info = g_rowinfo[row];
    const int   st   = info.x;
    const int   len  = info.y;
    const float nv   = g_norm[row];

    float ax = 0.f, ay = 0.f, az = 0.f, aw = 0.f;

    // ---- first (and usually only) batch of up to 16 edges ----
    const int n16 = (len < 16) ? len : 16;
    uint2 e = make_uint2(0u, 0u);
    if (sub < n16) e = g_edge[st + sub];

    #pragma unroll
    for (int j = 0; j < 16; j++) {
        unsigned s = __shfl_sync(0xFFFFFFFFu, e.x, j, 16);
        float    w = __uint_as_float(__shfl_sync(0xFFFFFFFFu, e.y, j, 16));
        if (j < n16) {
            float4 v = ((const float4*)(hsrc + (size_t)s * DD))[sub];
            ax = fmaf(w, v.x, ax);  ay = fmaf(w, v.y, ay);
            az = fmaf(w, v.z, az);  aw = fmaf(w, v.w, aw);
        }
    }

    // ---- rare deep rows (deg > 16): scalar tail ----
    for (int j = 16; j < len; j++) {
        uint2 e2 = g_edge[st + j];
        float  w = __uint_as_float(e2.y);
        float4 v = ((const float4*)(hsrc + (size_t)e2.x * DD))[sub];
        ax = fmaf(w, v.x, ax);  ay = fmaf(w, v.y, ay);
        az = fmaf(w, v.z, az);  aw = fmaf(w, v.w, aw);
    }

    // ---- epilogue: self loop + alpha*h0 ----
    float4 sh = ((const float4*)(hsrc + (size_t)row * DD))[sub];
    float4 x0 = ((const float4*)(x    + (size_t)row * DD))[sub];

    const float cn = BETA_C * nv;           // neighbor coefficient
    const float cs = BETA_C * nv * nv;      // self-loop coefficient

    float4 r;
    r.x = fmaf(cn, ax, fmaf(cs, sh.x, ALPHA_C * x0.x)) * fs;
    r.y = fmaf(cn, ay, fmaf(cs, sh.y, ALPHA_C * x0.y)) * fs;
    r.z = fmaf(cn, az, fmaf(cs, sh.z, ALPHA_C * x0.z)) * fs;
    r.w = fmaf(cn, aw, fmaf(cs, sh.w, ALPHA_C * x0.w)) * fs;

    ((float4*)(hdst + (size_t)row * DD))[sub] = r;
}

// --------------------------------- launch ----------------------------------
extern "C" void kernel_launch(void* const* d_in, const int* in_sizes, int n_in,
                              void* d_out, int out_size) {
    const float* x    = (const float*)d_in[0];
    const int*   uidx = (const int*)  d_in[1];
    const int*   iidx = (const int*)  d_in[2];
    float*       out  = (float*)d_out;

    const int T = 256;
    // ---- CSR build ----
    init_kernel <<<(NN + T - 1) / T, T>>>();
    count_kernel<<<(NE + T - 1) / T, T>>>(uidx, iidx);
    alloc_kernel<<<(NN + T - 1) / T, T>>>();
    fill_kernel <<<(NE + T - 1) / T, T>>>(uidx, iidx);

    // ---- K = 4 diffusion steps (2 rows per warp) ----
    const int rows_per_blk = (T / 32) * 2;            // 16 rows / block
    const int spmm_blocks  = (NN + rows_per_blk - 1) / rows_per_blk;
    spmm_kernel<<<spmm_blocks, T>>>(-1, 0, x, out, 1.0f);        // x    -> h[0]
    spmm_kernel<<<spmm_blocks, T>>>( 0, 1, x, out, 1.0f);        // h[0] -> h[1]
    spmm_kernel<<<spmm_blocks, T>>>( 1, 0, x, out, 1.0f);        // h[1] -> h[0]
    spmm_kernel<<<spmm_blocks, T>>>( 0, -1, x, out, INV_GAMMA);  // h[0] -> out
}

// round 3
// speedup vs baseline: 1.6206x; 1.2167x over previous
#include <cuda_runtime.h>
#include <cuda_fp16.h>
#include <cstdint>

// ---------------------------------------------------------------------------
// MGDCF diffusion: h_{t+1} = BETA * A_norm h_t + ALPHA * h0, K=4 steps.
// Round 3: intermediate h buffers in fp16 (fp32 accumulation, fp32 h0 term,
// fp32 final output) to halve gather/store traffic. SpMM: 16 lanes/row,
// batched edge fetch + shuffle broadcast, unrolled predicated gathers.
// ---------------------------------------------------------------------------

#define NUSERS 200000
#define NITEMS 100000
#define NN     300000              // total nodes (even -> exact warp tiling)
#define NE     1000000             // user-item pairs
#define DD     64                  // feature dim

static constexpr float ALPHA_C = 0.1f;
static constexpr float BETA_C  = 0.9f;
static constexpr double GAMMA_D =
    (0.9 * 0.9 * 0.9 * 0.9) + 0.1 * (1.0 + 0.9 + 0.81 + 0.729);   // = 1.0
static constexpr float INV_GAMMA = (float)(1.0 / GAMMA_D);

// ------------------------- device scratch (static) -------------------------
__device__ __half g_hh[2][(size_t)NN * DD];  // ping-pong fp16 h buffers (76.8 MB)
__device__ int    g_cnt[NN];                 // real in-degree (excl. self loop)
__device__ float  g_norm[NN];                // (deg incl. self)^-1/2
__device__ int2   g_rowinfo[NN];             // (segment start, real in-degree)
__device__ int    g_cursor[NN];              // fill cursors
__device__ uint2  g_edge[2 * NE];            // (src, norm[src] bits), 16 MB
__device__ int    g_alloc;                   // global segment allocator

// ------------------------------ build kernels ------------------------------

__global__ void init_kernel() {
    int v = blockIdx.x * blockDim.x + threadIdx.x;
    if (v < NN) g_cnt[v] = 0;
    if (v == 0) g_alloc = 0;
}

__global__ void count_kernel(const int* __restrict__ uidx,
                             const int* __restrict__ iidx) {
    int e = blockIdx.x * blockDim.x + threadIdx.x;
    if (e >= NE) return;
    int u  = uidx[e];
    int it = iidx[e] + NUSERS;
    atomicAdd(&g_cnt[u], 1);
    atomicAdd(&g_cnt[it], 1);
}

// Per-node: norm = rsqrt(deg+1); allocate contiguous CSR segment of length
// deg via warp-scanned atomicAdd on the global allocator.
__global__ void alloc_kernel() {
    int v    = blockIdx.x * blockDim.x + threadIdx.x;
    int lane = threadIdx.x & 31;
    int c = 0;
    if (v < NN) {
        c = g_cnt[v];                        // real in-edges
        g_norm[v] = rsqrtf((float)(c + 1));  // +1 self loop
    }
    int inc = c;
    #pragma unroll
    for (int o = 1; o < 32; o <<= 1) {
        int t = __shfl_up_sync(0xFFFFFFFFu, inc, o);
        if (lane >= o) inc += t;
    }
    int total = __shfl_sync(0xFFFFFFFFu, inc, 31);
    int base = 0;
    if (lane == 31) base = atomicAdd(&g_alloc, total);
    base = __shfl_sync(0xFFFFFFFFu, base, 31);
    if (v < NN) {
        int st = base + inc - c;
        g_rowinfo[v] = make_int2(st, c);
        g_cursor[v]  = st;
    }
}

__global__ void fill_kernel(const int* __restrict__ uidx,
                            const int* __restrict__ iidx) {
    int e = blockIdx.x * blockDim.x + threadIdx.x;
    if (e >= NE) return;
    int u  = uidx[e];
    int it = iidx[e] + NUSERS;
    float nu = g_norm[u];
    float ni = g_norm[it];
    int p0 = atomicAdd(&g_cursor[it], 1);
    g_edge[p0] = make_uint2((unsigned)u, __float_as_uint(nu));
    int p1 = atomicAdd(&g_cursor[u], 1);
    g_edge[p1] = make_uint2((unsigned)it, __float_as_uint(ni));
}

// ----------------------- typed row load/store helpers -----------------------

__device__ __forceinline__ float4 loadRow(const float* __restrict__ h,
                                          unsigned row, int sub) {
    return ((const float4*)(h + (size_t)row * DD))[sub];
}
__device__ __forceinline__ float4 loadRow(const __half* __restrict__ h,
                                          unsigned row, int sub) {
    uint2 r = ((const uint2*)(h + (size_t)row * DD))[sub];
    __half2 a = *(__half2*)&r.x;
    __half2 b = *(__half2*)&r.y;
    float2 fa = __half22float2(a);
    float2 fb = __half22float2(b);
    return make_float4(fa.x, fa.y, fb.x, fb.y);
}
__device__ __forceinline__ void storeRow(float* __restrict__ h,
                                         unsigned row, int sub, float4 v) {
    ((float4*)(h + (size_t)row * DD))[sub] = v;
}
__device__ __forceinline__ void storeRow(__half* __restrict__ h,
                                         unsigned row, int sub, float4 v) {
    __half2 a = __floats2half2_rn(v.x, v.y);
    __half2 b = __floats2half2_rn(v.z, v.w);
    uint2 r;
    r.x = *(unsigned*)&a;
    r.y = *(unsigned*)&b;
    ((uint2*)(h + (size_t)row * DD))[sub] = r;
}

// ------------------------------- SpMM kernel -------------------------------
// Two rows per warp: 16 lanes per destination row, each lane owns 4 columns.
// Edge batch fetched coalesced (one uint2 per lane), broadcast via width-16
// shuffles; gathers predicated + fully unrolled for deep MLP. fp32 accum.
template <typename SrcT, typename DstT>
__global__ void __launch_bounds__(256)
spmm_kernel(const SrcT* __restrict__ hsrc, DstT* __restrict__ hdst,
            const float* __restrict__ x, float fs) {
    const int lane = threadIdx.x & 31;
    const int sub  = lane & 15;
    const int half = lane >> 4;
    const int warp = blockIdx.x * (blockDim.x >> 5) + (threadIdx.x >> 5);
    const unsigned row = warp * 2 + half;
    if (row >= NN) return;

    const int2 info = g_rowinfo[row];
    const int  st   = info.x;
    const int  len  = info.y;
    const float nv  = rsqrtf((float)(len + 1));   // recompute, no g_norm load

    float ax = 0.f, ay = 0.f, az = 0.f, aw = 0.f;

    // ---- first (usually only) batch of up to 16 edges ----
    const int n16 = (len < 16) ? len : 16;
    uint2 e = make_uint2(0u, 0u);
    if (sub < n16) e = g_edge[st + sub];

    #pragma unroll
    for (int j = 0; j < 16; j++) {
        unsigned s = __shfl_sync(0xFFFFFFFFu, e.x, j, 16);
        float    w = __uint_as_float(__shfl_sync(0xFFFFFFFFu, e.y, j, 16));
        if (j < n16) {
            float4 v = loadRow(hsrc, s, sub);
            ax = fmaf(w, v.x, ax);  ay = fmaf(w, v.y, ay);
            az = fmaf(w, v.z, az);  aw = fmaf(w, v.w, aw);
        }
    }

    // ---- rare deep rows (deg > 16): scalar tail ----
    for (int j = 16; j < len; j++) {
        uint2 e2 = g_edge[st + j];
        float  w = __uint_as_float(e2.y);
        float4 v = loadRow(hsrc, e2.x, sub);
        ax = fmaf(w, v.x, ax);  ay = fmaf(w, v.y, ay);
        az = fmaf(w, v.z, az);  aw = fmaf(w, v.w, aw);
    }

    // ---- epilogue: self loop + alpha*h0 ----
    float4 sh = loadRow(hsrc, row, sub);
    float4 x0 = ((const float4*)(x + (size_t)row * DD))[sub];

    const float cn = BETA_C * nv;
    const float cs = BETA_C * nv * nv;

    float4 r;
    r.x = fmaf(cn, ax, fmaf(cs, sh.x, ALPHA_C * x0.x)) * fs;
    r.y = fmaf(cn, ay, fmaf(cs, sh.y, ALPHA_C * x0.y)) * fs;
    r.z = fmaf(cn, az, fmaf(cs, sh.z, ALPHA_C * x0.z)) * fs;
    r.w = fmaf(cn, aw, fmaf(cs, sh.w, ALPHA_C * x0.w)) * fs;

    storeRow(hdst, row, sub, r);
}

// --------------------------------- launch ----------------------------------
extern "C" void kernel_launch(void* const* d_in, const int* in_sizes, int n_in,
                              void* d_out, int out_size) {
    const float* x    = (const float*)d_in[0];
    const int*   uidx = (const int*)  d_in[1];
    const int*   iidx = (const int*)  d_in[2];
    float*       out  = (float*)d_out;

    const int T = 256;
    // ---- CSR build ----
    init_kernel <<<(NN + T - 1) / T, T>>>();
    count_kernel<<<(NE + T - 1) / T, T>>>(uidx, iidx);
    alloc_kernel<<<(NN + T - 1) / T, T>>>();
    fill_kernel <<<(NE + T - 1) / T, T>>>(uidx, iidx);

    // ---- K = 4 diffusion steps (fp16 intermediates, fp32 ends) ----
    const int rows_per_blk = (T / 32) * 2;            // 16 rows / block
    const int spmm_blocks  = (NN + rows_per_blk - 1) / rows_per_blk;

    __half* h0 = nullptr; __half* h1 = nullptr;
    cudaGetSymbolAddress((void**)&h0, g_hh);          // address query only
    h0 = (__half*)((char*)h0);                        // g_hh[0]
    h1 = h0 + (size_t)NN * DD;                        // g_hh[1]

    spmm_kernel<float,  __half><<<spmm_blocks, T>>>(x,  h0, x, 1.0f);
    spmm_kernel<__half, __half><<<spmm_blocks, T>>>(h0, h1, x, 1.0f);
    spmm_kernel<__half, __half><<<spmm_blocks, T>>>(h1, h0, x, 1.0f);
    spmm_kernel<__half, float ><<<spmm_blocks, T>>>(h0, out, x, INV_GAMMA);
}